// round 2
// baseline (speedup 1.0000x reference)
#include <cuda_runtime.h>
#include <cuda_bf16.h>
#include <math.h>

#define BB 8192
#define CC 512
#define NSLOT 32

// ---------------- scratch (no allocations allowed) ----------------
__device__ float g_Q   [BB*CC];
__device__ float g_WK  [BB*CC];
__device__ float g_WV  [BB*CC];
__device__ float g_retr[BB*CC];
__device__ float g_upd [BB*CC];
__device__ float g_ww  [BB*NSLOT];

// ---------------- bf16 tensor-core GEMM:  out[M,N] = A[M,K] @ W[N,K]^T ----------------
#define BM 128
#define BN 64
#define BK 32
#define ASTR 40   // padded smem stride (elems): conflict-free for b32 fragment loads

__device__ __forceinline__ uint2 cvt4(float4 v) {
    __nv_bfloat162 lo = __floats2bfloat162_rn(v.x, v.y);
    __nv_bfloat162 hi = __floats2bfloat162_rn(v.z, v.w);
    uint2 r;
    r.x = *reinterpret_cast<unsigned int*>(&lo);
    r.y = *reinterpret_cast<unsigned int*>(&hi);
    return r;
}

__device__ __forceinline__ void mma16816(float* d, const unsigned* a, const unsigned* b) {
    asm volatile(
        "mma.sync.aligned.m16n8k16.row.col.f32.bf16.bf16.f32 "
        "{%0,%1,%2,%3}, {%4,%5,%6,%7}, {%8,%9}, {%0,%1,%2,%3};\n"
        : "+f"(d[0]), "+f"(d[1]), "+f"(d[2]), "+f"(d[3])
        : "r"(a[0]), "r"(a[1]), "r"(a[2]), "r"(a[3]), "r"(b[0]), "r"(b[1]));
}

// MODE 0: plain store to out.
// MODE 1: gate epilogue: out[i,j] = sigmoid(eta[j]) * sigmoid(acc + b_gate[j]) * (wv[i,j] - retr[i,j])
//         A is concat([A0 (K<CC)], [A1 (K>=CC)]), each half stride CC.
template <int MODE>
__global__ void __launch_bounds__(256) gemm_bf16(
    const float* __restrict__ A0, const float* __restrict__ A1,
    const float* __restrict__ W, int K, int ldA,
    float* __restrict__ out,
    const float* __restrict__ bgate, const float* __restrict__ eta,
    const float* __restrict__ wv, const float* __restrict__ retr)
{
    __shared__ __nv_bfloat16 As[2][BM * ASTR];
    __shared__ __nv_bfloat16 Bs[2][BN * ASTR];

    const int tid  = threadIdx.x;
    const int warp = tid >> 5, lane = tid & 31;
    const int wm = warp >> 1, wn = warp & 1;      // 4x2 warp grid, warp tile 32x32
    const int g = lane >> 2, t = lane & 3;
    const int bm = blockIdx.y * BM, bn = blockIdx.x * BN;

    float acc[2][4][4];
#pragma unroll
    for (int i = 0; i < 2; i++)
#pragma unroll
        for (int j = 0; j < 4; j++)
#pragma unroll
            for (int k = 0; k < 4; k++) acc[i][j][k] = 0.f;

    float4 ra[4], rb[2];

    auto loadA = [&](int k0) {
#pragma unroll
        for (int it = 0; it < 4; it++) {
            int slot = tid + it * 256;
            int row = slot >> 3, c4 = slot & 7;
            int kk = k0 + c4 * 4;
            const float* p;
            if (MODE == 1 && kk >= CC) p = A1 + (size_t)(bm + row) * CC + (kk - CC);
            else                        p = A0 + (size_t)(bm + row) * ldA + kk;
            ra[it] = *reinterpret_cast<const float4*>(p);
        }
    };
    auto loadB = [&](int k0) {
#pragma unroll
        for (int it = 0; it < 2; it++) {
            int slot = tid + it * 256;
            int row = slot >> 3, c4 = slot & 7;
            rb[it] = *reinterpret_cast<const float4*>(W + (size_t)(bn + row) * K + k0 + c4 * 4);
        }
    };
    auto storeAB = [&](int buf) {
#pragma unroll
        for (int it = 0; it < 4; it++) {
            int slot = tid + it * 256;
            int row = slot >> 3, c4 = slot & 7;
            *reinterpret_cast<uint2*>(&As[buf][row * ASTR + c4 * 4]) = cvt4(ra[it]);
        }
#pragma unroll
        for (int it = 0; it < 2; it++) {
            int slot = tid + it * 256;
            int row = slot >> 3, c4 = slot & 7;
            *reinterpret_cast<uint2*>(&Bs[buf][row * ASTR + c4 * 4]) = cvt4(rb[it]);
        }
    };

    const int KT = K / BK;
    loadA(0); loadB(0);
    storeAB(0);
    __syncthreads();

    for (int kt = 0; kt < KT; kt++) {
        const int buf = kt & 1;
        if (kt + 1 < KT) { loadA((kt + 1) * BK); loadB((kt + 1) * BK); }

#pragma unroll
        for (int ks = 0; ks < 2; ks++) {
            const int kb = ks * 16;
            unsigned a[2][4], b[4][2];
#pragma unroll
            for (int mi = 0; mi < 2; mi++) {
                const int r0 = wm * 32 + mi * 16;
                a[mi][0] = *reinterpret_cast<const unsigned*>(&As[buf][(r0 + g    ) * ASTR + kb + 2 * t    ]);
                a[mi][1] = *reinterpret_cast<const unsigned*>(&As[buf][(r0 + g + 8) * ASTR + kb + 2 * t    ]);
                a[mi][2] = *reinterpret_cast<const unsigned*>(&As[buf][(r0 + g    ) * ASTR + kb + 2 * t + 8]);
                a[mi][3] = *reinterpret_cast<const unsigned*>(&As[buf][(r0 + g + 8) * ASTR + kb + 2 * t + 8]);
            }
#pragma unroll
            for (int ni = 0; ni < 4; ni++) {
                const int n0 = wn * 32 + ni * 8;
                b[ni][0] = *reinterpret_cast<const unsigned*>(&Bs[buf][(n0 + g) * ASTR + kb + 2 * t    ]);
                b[ni][1] = *reinterpret_cast<const unsigned*>(&Bs[buf][(n0 + g) * ASTR + kb + 2 * t + 8]);
            }
#pragma unroll
            for (int mi = 0; mi < 2; mi++)
#pragma unroll
                for (int ni = 0; ni < 4; ni++)
                    mma16816(acc[mi][ni], a[mi], b[ni]);
        }

        if (kt + 1 < KT) storeAB((kt + 1) & 1);
        __syncthreads();
    }

    // epilogue (N = CC for all our GEMMs)
#pragma unroll
    for (int mi = 0; mi < 2; mi++) {
#pragma unroll
        for (int ni = 0; ni < 4; ni++) {
            const int col  = bn + wn * 32 + ni * 8 + 2 * t;
            const int row0 = bm + wm * 32 + mi * 16 + g;
            const int row1 = row0 + 8;
            if (MODE == 0) {
                *reinterpret_cast<float2*>(&out[(size_t)row0 * CC + col]) =
                    make_float2(acc[mi][ni][0], acc[mi][ni][1]);
                *reinterpret_cast<float2*>(&out[(size_t)row1 * CC + col]) =
                    make_float2(acc[mi][ni][2], acc[mi][ni][3]);
            } else {
#pragma unroll
                for (int e = 0; e < 4; e++) {
                    const int r = (e < 2) ? row0 : row1;
                    const int c = col + (e & 1);
                    const float surprise = 1.f / (1.f + expf(-(acc[mi][ni][e] + bgate[c])));
                    const float eta_s    = 1.f / (1.f + expf(-eta[c]));
                    const size_t idx = (size_t)r * CC + c;
                    out[idx] = eta_s * surprise * (wv[idx] - retr[idx]);
                }
            }
        }
    }
}

// ---------------- fused attention / retrieval / Mk_new kernel ----------------
// one block per batch row b
__global__ void __launch_bounds__(256) attn_kernel(
    const float* __restrict__ h, const float* __restrict__ Q,
    const float* __restrict__ WK, const float* __restrict__ Mk,
    const float* __restrict__ Mm, float* __restrict__ out,
    float* __restrict__ retr, float* __restrict__ ww_g)
{
    const int b = blockIdx.x;
    __shared__ float qs[CC], wks[CC];
    __shared__ float sm[NSLOT], tm[NSLOT], attn[NSLOT], wws[NSLOT];

    const int tid = threadIdx.x;
    const int warp = tid >> 5, lane = tid & 31;
    const float* Qb  = Q  + (size_t)b * CC;
    const float* WKb = WK + (size_t)b * CC;
    const float* Mkb = Mk + (size_t)b * NSLOT * CC;
    const float* Mb  = Mm + (size_t)b * NSLOT * CC;

#pragma unroll
    for (int i = 0; i < 2; i++) {
        qs [tid + i * 256] = Qb [tid + i * 256];
        wks[tid + i * 256] = WKb[tid + i * 256];
    }
    __syncthreads();

    // dual dot products vs M_keys rows (warp -> 4 slots)
#pragma unroll
    for (int mm = 0; mm < 4; mm++) {
        const int m = warp * 4 + mm;
        const float* row = Mkb + (size_t)m * CC;
        float s = 0.f, tt = 0.f;
#pragma unroll
        for (int c = lane; c < CC; c += 32) {
            const float v = row[c];
            s  += v * qs [c];
            tt += v * wks[c];
        }
#pragma unroll
        for (int o = 16; o > 0; o >>= 1) {
            s  += __shfl_xor_sync(0xffffffffu, s,  o);
            tt += __shfl_xor_sync(0xffffffffu, tt, o);
        }
        if (lane == 0) { sm[m] = s; tm[m] = tt; }
    }
    __syncthreads();

    if (tid < 32) {
        const float isq = 1.0f / sqrtf((float)CC);
        float s = sm[tid] * isq;
        float w = tm[tid] * isq;
        float mx = s;
#pragma unroll
        for (int o = 16; o > 0; o >>= 1) mx = fmaxf(mx, __shfl_xor_sync(0xffffffffu, mx, o));
        float e = expf(s - mx), sum = e;
#pragma unroll
        for (int o = 16; o > 0; o >>= 1) sum += __shfl_xor_sync(0xffffffffu, sum, o);
        attn[tid] = e / sum;

        float mx2 = w;
#pragma unroll
        for (int o = 16; o > 0; o >>= 1) mx2 = fmaxf(mx2, __shfl_xor_sync(0xffffffffu, mx2, o));
        float e2 = expf(w - mx2), sum2 = e2;
#pragma unroll
        for (int o = 16; o > 0; o >>= 1) sum2 += __shfl_xor_sync(0xffffffffu, sum2, o);
        const float wv = e2 / sum2;
        wws[tid] = wv;
        ww_g[(size_t)b * NSLOT + tid] = wv;
    }
    __syncthreads();

    // retrieved + out
#pragma unroll
    for (int i = 0; i < 2; i++) {
        const int c = tid + i * 256;
        float r = 0.f;
#pragma unroll
        for (int m = 0; m < NSLOT; m++) r += attn[m] * Mb[(size_t)m * CC + c];
        retr[(size_t)b * CC + c] = r;
        out [(size_t)b * CC + c] = h[(size_t)b * CC + c] + r;
    }

    // Mk_new (section 2 of output): Mk + w_m * (wk_c - Mk) * 0.01
    float* mkout = out + (size_t)BB * CC + (size_t)BB * NSLOT * CC + (size_t)b * NSLOT * CC;
    for (int idx = tid; idx < NSLOT * CC; idx += 256) {
        const int m = idx >> 9, c = idx & (CC - 1);
        const float mkv = Mkb[idx];
        mkout[idx] = mkv + wws[m] * (wks[c] - mkv) * 0.01f;
    }
}

// ---------------- M update: M_new = M + w_m * upd_c ----------------
__global__ void __launch_bounds__(256) mupd_kernel(
    const float* __restrict__ Mm, const float* __restrict__ upd,
    const float* __restrict__ ww_g, float* __restrict__ mnew)
{
    const int b = blockIdx.x;
    __shared__ float us[CC];
    __shared__ float wws[NSLOT];
    const int tid = threadIdx.x;
#pragma unroll
    for (int i = 0; i < 2; i++) us[tid + i * 256] = upd[(size_t)b * CC + tid + i * 256];
    if (tid < NSLOT) wws[tid] = ww_g[(size_t)b * NSLOT + tid];
    __syncthreads();

    const float* Mb = Mm   + (size_t)b * NSLOT * CC;
    float*       ob = mnew + (size_t)b * NSLOT * CC;
    for (int idx = tid; idx < NSLOT * CC; idx += 256) {
        const int m = idx >> 9, c = idx & (CC - 1);
        ob[idx] = Mb[idx] + wws[m] * us[c];
    }
}

// ---------------- launch ----------------
extern "C" void kernel_launch(void* const* d_in, const int* in_sizes, int n_in,
                              void* d_out, int out_size)
{
    const float* h   = (const float*)d_in[0];
    const float* p   = (const float*)d_in[1];
    const float* M   = (const float*)d_in[2];
    const float* Mk  = (const float*)d_in[3];
    const float* Wq  = (const float*)d_in[4];
    const float* Wk  = (const float*)d_in[5];
    const float* Wv  = (const float*)d_in[6];
    const float* Wg  = (const float*)d_in[7];
    const float* bg  = (const float*)d_in[8];
    const float* eta = (const float*)d_in[9];
    float* out = (float*)d_out;

    float *Q_, *WK_, *WV_, *retr_, *upd_, *ww_;
    cudaGetSymbolAddress((void**)&Q_,    g_Q);
    cudaGetSymbolAddress((void**)&WK_,   g_WK);
    cudaGetSymbolAddress((void**)&WV_,   g_WV);
    cudaGetSymbolAddress((void**)&retr_, g_retr);
    cudaGetSymbolAddress((void**)&upd_,  g_upd);
    cudaGetSymbolAddress((void**)&ww_,   g_ww);

    dim3 ggrid(CC / BN, BB / BM);

    // projections: Q = h @ Wq^T, WK = p @ Wk^T, WV = p @ Wv^T
    gemm_bf16<0><<<ggrid, 256>>>(h, nullptr, Wq, CC, CC, Q_,  nullptr, nullptr, nullptr, nullptr);
    gemm_bf16<0><<<ggrid, 256>>>(p, nullptr, Wk, CC, CC, WK_, nullptr, nullptr, nullptr, nullptr);
    gemm_bf16<0><<<ggrid, 256>>>(p, nullptr, Wv, CC, CC, WV_, nullptr, nullptr, nullptr, nullptr);

    // fused attention / retrieval / out / Mk_new
    attn_kernel<<<BB, 256>>>(h, Q_, WK_, Mk, M, out, retr_, ww_);

    // gate GEMM on [retrieved, pooled] with fused surprise/update epilogue
    gemm_bf16<1><<<ggrid, 256>>>(retr_, p, Wg, 2 * CC, CC, upd_, bg, eta, WV_, retr_);

    // M_new
    mupd_kernel<<<BB, 256>>>(M, upd_, ww_, out + (size_t)BB * CC);
}

// round 5
// speedup vs baseline: 1.2460x; 1.2460x over previous
#include <cuda_runtime.h>
#include <cuda_bf16.h>
#include <math.h>

#define BB 8192
#define CC 512
#define NSLOT 32

// ---------------- scratch (no allocations allowed) ----------------
__device__ float g_Q   [BB*CC];
__device__ float g_WK  [BB*CC];
__device__ float g_WV  [BB*CC];
__device__ float g_retr[BB*CC];
__device__ float g_ww  [BB*NSLOT];
__device__ float g_etas[CC];
__device__ __nv_bfloat16 g_hb   [BB*CC];
__device__ __nv_bfloat16 g_pb   [BB*CC];
__device__ __nv_bfloat16 g_retrb[BB*CC];
__device__ __nv_bfloat16 g_Wqb  [CC*CC];
__device__ __nv_bfloat16 g_Wkb  [CC*CC];
__device__ __nv_bfloat16 g_Wvb  [CC*CC];
__device__ __nv_bfloat16 g_Wgb  [2*CC*CC];

// ---------------- helpers ----------------
__device__ __forceinline__ uint2 cvt4(float4 v) {
    __nv_bfloat162 lo = __floats2bfloat162_rn(v.x, v.y);
    __nv_bfloat162 hi = __floats2bfloat162_rn(v.z, v.w);
    uint2 r;
    r.x = *reinterpret_cast<unsigned int*>(&lo);
    r.y = *reinterpret_cast<unsigned int*>(&hi);
    return r;
}

__device__ __forceinline__ unsigned smem_u32(const void* p) {
    unsigned a;
    asm volatile("{ .reg .u64 t; cvta.to.shared.u64 t, %1; cvt.u32.u64 %0, t; }"
                 : "=r"(a) : "l"(p));
    return a;
}

__device__ __forceinline__ void cp16(unsigned dst, const void* src) {
    asm volatile("cp.async.cg.shared.global [%0], [%1], 16;" :: "r"(dst), "l"(src));
}
#define CP_COMMIT() asm volatile("cp.async.commit_group;" ::)
#define CP_WAIT1()  asm volatile("cp.async.wait_group 1;" ::)
#define CP_WAIT0()  asm volatile("cp.async.wait_group 0;" ::)

__device__ __forceinline__ void ldsm4(unsigned* r, unsigned a) {
    asm volatile("ldmatrix.sync.aligned.m8n8.x4.shared.b16 {%0,%1,%2,%3}, [%4];"
                 : "=r"(r[0]), "=r"(r[1]), "=r"(r[2]), "=r"(r[3]) : "r"(a));
}

__device__ __forceinline__ void mma16816(float* d, const unsigned* a, const unsigned* b) {
    asm volatile(
        "mma.sync.aligned.m16n8k16.row.col.f32.bf16.bf16.f32 "
        "{%0,%1,%2,%3}, {%4,%5,%6,%7}, {%8,%9}, {%0,%1,%2,%3};\n"
        : "+f"(d[0]), "+f"(d[1]), "+f"(d[2]), "+f"(d[3])
        : "r"(a[0]), "r"(a[1]), "r"(a[2]), "r"(a[3]), "r"(b[0]), "r"(b[1]));
}

// ---------------- one-shot bf16 conversion ----------------
__global__ void __launch_bounds__(256) convert_kernel(
    const float* __restrict__ h, const float* __restrict__ p,
    const float* __restrict__ Wq, const float* __restrict__ Wk,
    const float* __restrict__ Wv, const float* __restrict__ Wg,
    const float* __restrict__ eta)
{
    if (blockIdx.x == 0 && threadIdx.x < 256) {
        for (int c = threadIdx.x; c < CC; c += 256)
            g_etas[c] = 1.f / (1.f + __expf(-eta[c]));
    }
    int i = blockIdx.x * 256 + threadIdx.x;
    const float4* src; __nv_bfloat16* dst; int off;
    if      (i < 1048576) { src = (const float4*)h;  dst = g_hb;  off = 0;       }
    else if (i < 2097152) { src = (const float4*)p;  dst = g_pb;  off = 1048576; }
    else if (i < 2162688) { src = (const float4*)Wq; dst = g_Wqb; off = 2097152; }
    else if (i < 2228224) { src = (const float4*)Wk; dst = g_Wkb; off = 2162688; }
    else if (i < 2293760) { src = (const float4*)Wv; dst = g_Wvb; off = 2228224; }
    else                  { src = (const float4*)Wg; dst = g_Wgb; off = 2293760; }
    int j = i - off;
    *reinterpret_cast<uint2*>(dst + 4 * (size_t)j) = cvt4(src[j]);
}

// ---------------- GEMM mainloop (BM=BN=128, BK=32, 3-stage cp.async) ----------------
// smem row = 32 bf16 padded to 80B. A-stage 10240B x3 at sbase, B-stages at sbase+30720.
// A1 != nullptr -> concat A ([A0 | A1], each half row-stride CC) for K=2*CC gate GEMM.
__device__ __forceinline__ void gemm_mainloop(
    const __nv_bfloat16* A0, const __nv_bfloat16* A1,
    const __nv_bfloat16* W, int K, int bm, int bn,
    unsigned sbase, int tid, int wrow, int wcol, int lane,
    float acc[4][4][4])
{
    const int KT = K / 32;
#pragma unroll
    for (int pre = 0; pre < 2; pre++) {
        const int k0 = pre * 32;
        const __nv_bfloat16* Ab = (A1 != nullptr && k0 >= CC) ? (A1 + (k0 - CC)) : (A0 + k0);
        const unsigned as = sbase + pre * 10240;
        const unsigned bs = sbase + 30720 + pre * 10240;
#pragma unroll
        for (int i = 0; i < 2; i++) {
            int slot = tid + i * 256;
            int row = slot >> 2, ch = slot & 3;
            cp16(as + row * 80 + ch * 16, Ab + (size_t)(bm + row) * CC + ch * 8);
            cp16(bs + row * 80 + ch * 16, W + (size_t)(bn + row) * K + k0 + ch * 8);
        }
        CP_COMMIT();
    }

    for (int kt = 0; kt < KT; kt++) {
        CP_WAIT1();
        __syncthreads();
        const unsigned as = sbase + (kt % 3) * 10240;
        const unsigned bs = sbase + 30720 + (kt % 3) * 10240;
#pragma unroll
        for (int ks = 0; ks < 2; ks++) {
            unsigned a[4][4], b[4][2], r[4];
#pragma unroll
            for (int mi = 0; mi < 4; mi++)
                ldsm4(a[mi], as + (unsigned)((wrow + mi * 16 + (lane & 15)) * 80
                                             + (2 * ks + (lane >> 4)) * 16));
#pragma unroll
            for (int pp = 0; pp < 2; pp++) {
                ldsm4(r, bs + (unsigned)((wcol + pp * 16 + (lane & 7) + ((lane >> 4) << 3)) * 80
                                         + (2 * ks + ((lane >> 3) & 1)) * 16));
                b[2*pp][0] = r[0]; b[2*pp][1] = r[1];
                b[2*pp+1][0] = r[2]; b[2*pp+1][1] = r[3];
            }
#pragma unroll
            for (int mi = 0; mi < 4; mi++)
#pragma unroll
                for (int ni = 0; ni < 4; ni++)
                    mma16816(acc[mi][ni], a[mi], b[ni]);
        }
        if (kt + 2 < KT) {
            const int k2 = kt + 2, k0 = k2 * 32;
            const __nv_bfloat16* Ab = (A1 != nullptr && k0 >= CC) ? (A1 + (k0 - CC)) : (A0 + k0);
            const unsigned as2 = sbase + (k2 % 3) * 10240;
            const unsigned bs2 = sbase + 30720 + (k2 % 3) * 10240;
#pragma unroll
            for (int i = 0; i < 2; i++) {
                int slot = tid + i * 256;
                int row = slot >> 2, ch = slot & 3;
                cp16(as2 + row * 80 + ch * 16, Ab + (size_t)(bm + row) * CC + ch * 8);
                cp16(bs2 + row * 80 + ch * 16, W + (size_t)(bn + row) * K + k0 + ch * 8);
            }
        }
        CP_COMMIT();
    }
    CP_WAIT0();
    __syncthreads();
}

// ---------------- projections: 3 GEMMs batched over blockIdx.z ----------------
__global__ void __launch_bounds__(256) gemm_proj()
{
    extern __shared__ char smem_p[];
    const unsigned sbase = smem_u32(smem_p);
    const int tid = threadIdx.x, warp = tid >> 5, lane = tid & 31;
    const int wrow = (warp >> 2) * 64, wcol = (warp & 3) * 32;
    const int bm = blockIdx.y * 128, bn = blockIdx.x * 128;

    const __nv_bfloat16* A = (blockIdx.z == 0) ? g_hb : g_pb;
    const __nv_bfloat16* W = (blockIdx.z == 0) ? g_Wqb : ((blockIdx.z == 1) ? g_Wkb : g_Wvb);
    float* out = (blockIdx.z == 0) ? g_Q : ((blockIdx.z == 1) ? g_WK : g_WV);

    float acc[4][4][4];
#pragma unroll
    for (int i = 0; i < 4; i++)
#pragma unroll
        for (int j = 0; j < 4; j++)
#pragma unroll
            for (int k = 0; k < 4; k++) acc[i][j][k] = 0.f;

    gemm_mainloop(A, nullptr, W, CC, bm, bn, sbase, tid, wrow, wcol, lane, acc);

    const int g = lane >> 2, t = lane & 3;
#pragma unroll
    for (int mi = 0; mi < 4; mi++)
#pragma unroll
        for (int ni = 0; ni < 4; ni++) {
            int r0 = bm + wrow + mi * 16 + g;
            int c  = bn + wcol + ni * 8 + 2 * t;
            *reinterpret_cast<float2*>(&out[(size_t)r0 * CC + c]) =
                make_float2(acc[mi][ni][0], acc[mi][ni][1]);
            *reinterpret_cast<float2*>(&out[(size_t)(r0 + 8) * CC + c]) =
                make_float2(acc[mi][ni][2], acc[mi][ni][3]);
        }
}

// ---------------- gate GEMM (K=2C) + fused surprise epilogue + M_new streaming ----------------
#define USTR 132
__global__ void __launch_bounds__(256) gemm_gate(
    const float* __restrict__ bg, const float* __restrict__ Mm,
    float* __restrict__ mnew)
{
    extern __shared__ char smem_g[];
    const unsigned sbase = smem_u32(smem_g);
    const int tid = threadIdx.x, warp = tid >> 5, lane = tid & 31;
    const int wrow = (warp >> 2) * 64, wcol = (warp & 3) * 32;
    const int bm = blockIdx.y * 128, bn = blockIdx.x * 128;

    float acc[4][4][4];
#pragma unroll
    for (int i = 0; i < 4; i++)
#pragma unroll
        for (int j = 0; j < 4; j++)
#pragma unroll
            for (int k = 0; k < 4; k++) acc[i][j][k] = 0.f;

    gemm_mainloop(g_retrb, g_pb, g_Wgb, 2 * CC, bm, bn, sbase, tid, wrow, wcol, lane, acc);

    float* upd_s = (float*)smem_g;                       // 128 x USTR
    float* ww_s  = (float*)(smem_g + 128 * USTR * 4);    // 128 x 32

    const int g = lane >> 2, t = lane & 3;
#pragma unroll
    for (int mi = 0; mi < 4; mi++)
#pragma unroll
        for (int ni = 0; ni < 4; ni++) {
            int rl0 = wrow + mi * 16 + g;
            int cl  = wcol + ni * 8 + 2 * t;
            int gc  = bn + cl;
            float e0 = g_etas[gc], e1 = g_etas[gc + 1];
            float b0 = bg[gc],     b1 = bg[gc + 1];
#pragma unroll
            for (int hh = 0; hh < 2; hh++) {
                int rl = rl0 + hh * 8;
                size_t gi = (size_t)(bm + rl) * CC + gc;
                float2 wv2 = *reinterpret_cast<const float2*>(&g_WV[gi]);
                float2 rt2 = *reinterpret_cast<const float2*>(&g_retr[gi]);
                float s0 = 1.f / (1.f + __expf(-(acc[mi][ni][hh*2+0] + b0)));
                float s1 = 1.f / (1.f + __expf(-(acc[mi][ni][hh*2+1] + b1)));
                upd_s[rl * USTR + cl]     = e0 * s0 * (wv2.x - rt2.x);
                upd_s[rl * USTR + cl + 1] = e1 * s1 * (wv2.y - rt2.y);
            }
        }
    {
        const float4* wwg4 = (const float4*)(g_ww + (size_t)bm * NSLOT);
#pragma unroll
        for (int i = 0; i < 4; i++)
            ((float4*)ww_s)[tid + i * 256] = wwg4[tid + i * 256];
    }
    __syncthreads();

    // M_new[b, m, bn..bn+128) = M + ww[b,m] * upd[b, .]
    const float4* M4 = (const float4*)Mm;
    float4* O4 = (float4*)mnew;
#pragma unroll 4
    for (int idx = tid; idx < 128 * NSLOT * 32; idx += 256) {
        int bl  = idx >> 10;
        int rem = idx & 1023;
        int m   = rem >> 5;
        int c4  = rem & 31;
        size_t gi = ((size_t)(bm + bl) * NSLOT + m) * (CC / 4) + (bn >> 2) + c4;
        float wwv = ww_s[bl * NSLOT + m];
        const float* up = &upd_s[bl * USTR + c4 * 4];
        float4 u = make_float4(up[0], up[1], up[2], up[3]);
        float4 mv = M4[gi];
        float4 o;
        o.x = mv.x + wwv * u.x;
        o.y = mv.y + wwv * u.y;
        o.z = mv.z + wwv * u.z;
        o.w = mv.w + wwv * u.w;
        O4[gi] = o;
    }
}

// ---------------- fused attention / retrieval / Mk_new ----------------
__global__ void __launch_bounds__(256) attn_kernel(
    const float* __restrict__ h, const float* __restrict__ Mk,
    const float* __restrict__ Mm, float* __restrict__ out)
{
    const int b = blockIdx.x;
    __shared__ float qs[CC], wks[CC];
    __shared__ float sm[NSLOT], tm[NSLOT], attnv[NSLOT], wws[NSLOT];

    const int tid = threadIdx.x;
    const int warp = tid >> 5, lane = tid & 31;
    const float* Mkb = Mk + (size_t)b * NSLOT * CC;
    const float* Mb  = Mm + (size_t)b * NSLOT * CC;

#pragma unroll
    for (int i = 0; i < 2; i++) {
        qs [tid + i * 256] = g_Q [(size_t)b * CC + tid + i * 256];
        wks[tid + i * 256] = g_WK[(size_t)b * CC + tid + i * 256];
    }
    __syncthreads();

    // dual dot products vs M_keys rows (warp -> 4 slots)
#pragma unroll
    for (int mm = 0; mm < 4; mm++) {
        const int m = warp * 4 + mm;
        const float4* row4 = (const float4*)(Mkb + (size_t)m * CC);
        float s = 0.f, tt = 0.f;
#pragma unroll
        for (int it = 0; it < 4; it++) {
            float4 v = row4[lane + it * 32];
            float4 q = ((const float4*)qs)[lane + it * 32];
            float4 w = ((const float4*)wks)[lane + it * 32];
            s  += v.x*q.x + v.y*q.y + v.z*q.z + v.w*q.w;
            tt += v.x*w.x + v.y*w.y + v.z*w.z + v.w*w.w;
        }
#pragma unroll
        for (int o = 16; o > 0; o >>= 1) {
            s  += __shfl_xor_sync(0xffffffffu, s,  o);
            tt += __shfl_xor_sync(0xffffffffu, tt, o);
        }
        if (lane == 0) { sm[m] = s; tm[m] = tt; }
    }
    __syncthreads();

    if (tid < 32) {
        const float isq = 1.0f / sqrtf((float)CC);
        float s = sm[tid] * isq;
        float w = tm[tid] * isq;
        float mx = s;
#pragma unroll
        for (int o = 16; o > 0; o >>= 1) mx = fmaxf(mx, __shfl_xor_sync(0xffffffffu, mx, o));
        float e = expf(s - mx), sum = e;
#pragma unroll
        for (int o = 16; o > 0; o >>= 1) sum += __shfl_xor_sync(0xffffffffu, sum, o);
        attnv[tid] = e / sum;

        float mx2 = w;
#pragma unroll
        for (int o = 16; o > 0; o >>= 1) mx2 = fmaxf(mx2, __shfl_xor_sync(0xffffffffu, mx2, o));
        float e2 = expf(w - mx2), sum2 = e2;
#pragma unroll
        for (int o = 16; o > 0; o >>= 1) sum2 += __shfl_xor_sync(0xffffffffu, sum2, o);
        const float wv = e2 / sum2;
        wws[tid] = wv;
        g_ww[(size_t)b * NSLOT + tid] = wv;
    }
    __syncthreads();

    // Mk_new FIRST (Mk still hot in L2 from the dot-product phase)
    {
        float* mkout = out + (size_t)BB * CC + (size_t)BB * NSLOT * CC + (size_t)b * NSLOT * CC;
        const float4* Mk4 = (const float4*)Mkb;
        float4* mo4 = (float4*)mkout;
        for (int idx = tid; idx < NSLOT * CC / 4; idx += 256) {
            const int m = idx >> 7;
            const int c4 = idx & 127;
            float4 mk = Mk4[idx];
            float4 wk = ((const float4*)wks)[c4];
            float w = wws[m] * 0.01f;
            float4 o;
            o.x = mk.x + w * (wk.x - mk.x);
            o.y = mk.y + w * (wk.y - mk.y);
            o.z = mk.z + w * (wk.z - mk.z);
            o.w = mk.w + w * (wk.w - mk.w);
            mo4[idx] = o;
        }
    }

    // retrieval (streams M) + out + bf16 retr for gate GEMM
    {
        const float2* M2 = (const float2*)Mb;
        float2 r = make_float2(0.f, 0.f);
#pragma unroll
        for (int m = 0; m < NSLOT; m++) {
            float2 v = M2[m * (CC / 2) + tid];
            r.x += attnv[m] * v.x;
            r.y += attnv[m] * v.y;
        }
        ((float2*)(g_retr + (size_t)b * CC))[tid] = r;
        const float2* h2 = (const float2*)(h + (size_t)b * CC);
        float2 hv = h2[tid];
        ((float2*)(out + (size_t)b * CC))[tid] = make_float2(hv.x + r.x, hv.y + r.y);
        __nv_bfloat162 rb = __floats2bfloat162_rn(r.x, r.y);
        ((__nv_bfloat162*)(g_retrb + (size_t)b * CC))[tid] = rb;
    }
}

// ---------------- launch ----------------
extern "C" void kernel_launch(void* const* d_in, const int* in_sizes, int n_in,
                              void* d_out, int out_size)
{
    const float* h   = (const float*)d_in[0];
    const float* p   = (const float*)d_in[1];
    const float* M   = (const float*)d_in[2];
    const float* Mk  = (const float*)d_in[3];
    const float* Wq  = (const float*)d_in[4];
    const float* Wk  = (const float*)d_in[5];
    const float* Wv  = (const float*)d_in[6];
    const float* Wg  = (const float*)d_in[7];
    const float* bg  = (const float*)d_in[8];
    const float* eta = (const float*)d_in[9];
    float* out = (float*)d_out;

    static int configured = 0;
    if (!configured) {
        cudaFuncSetAttribute(gemm_proj, cudaFuncAttributeMaxDynamicSharedMemorySize, 61440);
        cudaFuncSetAttribute(gemm_gate, cudaFuncAttributeMaxDynamicSharedMemorySize,
                             128 * USTR * 4 + 16384);
        configured = 1;
    }

    // 1. bf16 conversion (+ eta sigmoid)
    convert_kernel<<<9472, 256>>>(h, p, Wq, Wk, Wv, Wg, eta);

    // 2. Q / write_k / write_v projections (batched over z)
    gemm_proj<<<dim3(4, 64, 3), 256, 61440>>>();

    // 3. fused attention / retrieval / out / Mk_new
    attn_kernel<<<BB, 256>>>(h, Mk, M, out);

    // 4. gate GEMM with fused surprise/update epilogue + M_new streaming
    gemm_gate<<<dim3(4, 64, 1), 256, 128 * USTR * 4 + 16384>>>(
        bg, M, out + (size_t)BB * CC);
}

// round 6
// speedup vs baseline: 1.2747x; 1.0230x over previous
#include <cuda_runtime.h>
#include <cuda_bf16.h>
#include <math.h>

#define BB 8192
#define CC 512
#define NSLOT 32

// ---------------- scratch (no allocations allowed) ----------------
__device__ float g_Q   [BB*CC];
__device__ float g_WK  [BB*CC];
__device__ float g_WV  [BB*CC];
__device__ float g_upd [BB*CC];
__device__ float g_ww  [BB*NSLOT];
__device__ float g_etas[CC];
__device__ __nv_bfloat16 g_hb   [BB*CC];
__device__ __nv_bfloat16 g_pb   [BB*CC];
__device__ __nv_bfloat16 g_retrb[BB*CC];
__device__ __nv_bfloat16 g_Wqb  [CC*CC];
__device__ __nv_bfloat16 g_Wkb  [CC*CC];
__device__ __nv_bfloat16 g_Wvb  [CC*CC];
__device__ __nv_bfloat16 g_Wgb  [2*CC*CC];

// ---------------- helpers ----------------
__device__ __forceinline__ uint2 cvt4(float4 v) {
    __nv_bfloat162 lo = __floats2bfloat162_rn(v.x, v.y);
    __nv_bfloat162 hi = __floats2bfloat162_rn(v.z, v.w);
    uint2 r;
    r.x = *reinterpret_cast<unsigned int*>(&lo);
    r.y = *reinterpret_cast<unsigned int*>(&hi);
    return r;
}

__device__ __forceinline__ unsigned smem_u32(const void* p) {
    unsigned a;
    asm volatile("{ .reg .u64 t; cvta.to.shared.u64 t, %1; cvt.u32.u64 %0, t; }"
                 : "=r"(a) : "l"(p));
    return a;
}

__device__ __forceinline__ void cp16(unsigned dst, const void* src) {
    asm volatile("cp.async.cg.shared.global [%0], [%1], 16;" :: "r"(dst), "l"(src));
}
#define CP_COMMIT() asm volatile("cp.async.commit_group;" ::)
#define CP_WAIT1()  asm volatile("cp.async.wait_group 1;" ::)
#define CP_WAIT0()  asm volatile("cp.async.wait_group 0;" ::)

__device__ __forceinline__ void ldsm4(unsigned* r, unsigned a) {
    asm volatile("ldmatrix.sync.aligned.m8n8.x4.shared.b16 {%0,%1,%2,%3}, [%4];"
                 : "=r"(r[0]), "=r"(r[1]), "=r"(r[2]), "=r"(r[3]) : "r"(a));
}

__device__ __forceinline__ void mma16816(float* d, const unsigned* a, const unsigned* b) {
    asm volatile(
        "mma.sync.aligned.m16n8k16.row.col.f32.bf16.bf16.f32 "
        "{%0,%1,%2,%3}, {%4,%5,%6,%7}, {%8,%9}, {%0,%1,%2,%3};\n"
        : "+f"(d[0]), "+f"(d[1]), "+f"(d[2]), "+f"(d[3])
        : "r"(a[0]), "r"(a[1]), "r"(a[2]), "r"(a[3]), "r"(b[0]), "r"(b[1]));
}

// ---------------- one-shot bf16 conversion ----------------
__global__ void __launch_bounds__(256) convert_kernel(
    const float* __restrict__ h, const float* __restrict__ p,
    const float* __restrict__ Wq, const float* __restrict__ Wk,
    const float* __restrict__ Wv, const float* __restrict__ Wg,
    const float* __restrict__ eta)
{
    if (blockIdx.x == 0 && threadIdx.x < 256) {
        for (int c = threadIdx.x; c < CC; c += 256)
            g_etas[c] = 1.f / (1.f + __expf(-eta[c]));
    }
    int i = blockIdx.x * 256 + threadIdx.x;
    const float4* src; __nv_bfloat16* dst; int off;
    if      (i < 1048576) { src = (const float4*)h;  dst = g_hb;  off = 0;       }
    else if (i < 2097152) { src = (const float4*)p;  dst = g_pb;  off = 1048576; }
    else if (i < 2162688) { src = (const float4*)Wq; dst = g_Wqb; off = 2097152; }
    else if (i < 2228224) { src = (const float4*)Wk; dst = g_Wkb; off = 2162688; }
    else if (i < 2293760) { src = (const float4*)Wv; dst = g_Wvb; off = 2228224; }
    else                  { src = (const float4*)Wg; dst = g_Wgb; off = 2293760; }
    int j = i - off;
    *reinterpret_cast<uint2*>(dst + 4 * (size_t)j) = cvt4(src[j]);
}

// ---------------- GEMM mainloop (BM=BN=128, BK=32, 3-stage cp.async) ----------------
__device__ __forceinline__ void gemm_mainloop(
    const __nv_bfloat16* A0, const __nv_bfloat16* A1,
    const __nv_bfloat16* W, int K, int bm, int bn,
    unsigned sbase, int tid, int wrow, int wcol, int lane,
    float acc[4][4][4])
{
    const int KT = K / 32;
#pragma unroll
    for (int pre = 0; pre < 2; pre++) {
        const int k0 = pre * 32;
        const __nv_bfloat16* Ab = (A1 != nullptr && k0 >= CC) ? (A1 + (k0 - CC)) : (A0 + k0);
        const unsigned as = sbase + pre * 10240;
        const unsigned bs = sbase + 30720 + pre * 10240;
#pragma unroll
        for (int i = 0; i < 2; i++) {
            int slot = tid + i * 256;
            int row = slot >> 2, ch = slot & 3;
            cp16(as + row * 80 + ch * 16, Ab + (size_t)(bm + row) * CC + ch * 8);
            cp16(bs + row * 80 + ch * 16, W + (size_t)(bn + row) * K + k0 + ch * 8);
        }
        CP_COMMIT();
    }

    for (int kt = 0; kt < KT; kt++) {
        CP_WAIT1();
        __syncthreads();
        const unsigned as = sbase + (kt % 3) * 10240;
        const unsigned bs = sbase + 30720 + (kt % 3) * 10240;
#pragma unroll
        for (int ks = 0; ks < 2; ks++) {
            unsigned a[4][4], b[4][2], r[4];
#pragma unroll
            for (int mi = 0; mi < 4; mi++)
                ldsm4(a[mi], as + (unsigned)((wrow + mi * 16 + (lane & 15)) * 80
                                             + (2 * ks + (lane >> 4)) * 16));
#pragma unroll
            for (int pp = 0; pp < 2; pp++) {
                ldsm4(r, bs + (unsigned)((wcol + pp * 16 + (lane & 7) + ((lane >> 4) << 3)) * 80
                                         + (2 * ks + ((lane >> 3) & 1)) * 16));
                b[2*pp][0] = r[0]; b[2*pp][1] = r[1];
                b[2*pp+1][0] = r[2]; b[2*pp+1][1] = r[3];
            }
#pragma unroll
            for (int mi = 0; mi < 4; mi++)
#pragma unroll
                for (int ni = 0; ni < 4; ni++)
                    mma16816(acc[mi][ni], a[mi], b[ni]);
        }
        if (kt + 2 < KT) {
            const int k2 = kt + 2, k0 = k2 * 32;
            const __nv_bfloat16* Ab = (A1 != nullptr && k0 >= CC) ? (A1 + (k0 - CC)) : (A0 + k0);
            const unsigned as2 = sbase + (k2 % 3) * 10240;
            const unsigned bs2 = sbase + 30720 + (k2 % 3) * 10240;
#pragma unroll
            for (int i = 0; i < 2; i++) {
                int slot = tid + i * 256;
                int row = slot >> 2, ch = slot & 3;
                cp16(as2 + row * 80 + ch * 16, Ab + (size_t)(bm + row) * CC + ch * 8);
                cp16(bs2 + row * 80 + ch * 16, W + (size_t)(bn + row) * K + k0 + ch * 8);
            }
        }
        CP_COMMIT();
    }
    CP_WAIT0();
    __syncthreads();
}

// ---------------- projections: 3 GEMMs batched over blockIdx.z ----------------
__global__ void __launch_bounds__(256) gemm_proj()
{
    extern __shared__ char smem_p[];
    const unsigned sbase = smem_u32(smem_p);
    const int tid = threadIdx.x, warp = tid >> 5, lane = tid & 31;
    const int wrow = (warp >> 2) * 64, wcol = (warp & 3) * 32;
    const int bm = blockIdx.y * 128, bn = blockIdx.x * 128;

    const __nv_bfloat16* A = (blockIdx.z == 0) ? g_hb : g_pb;
    const __nv_bfloat16* W = (blockIdx.z == 0) ? g_Wqb : ((blockIdx.z == 1) ? g_Wkb : g_Wvb);
    float* out = (blockIdx.z == 0) ? g_Q : ((blockIdx.z == 1) ? g_WK : g_WV);

    float acc[4][4][4];
#pragma unroll
    for (int i = 0; i < 4; i++)
#pragma unroll
        for (int j = 0; j < 4; j++)
#pragma unroll
            for (int k = 0; k < 4; k++) acc[i][j][k] = 0.f;

    gemm_mainloop(A, nullptr, W, CC, bm, bn, sbase, tid, wrow, wcol, lane, acc);

    const int g = lane >> 2, t = lane & 3;
#pragma unroll
    for (int mi = 0; mi < 4; mi++)
#pragma unroll
        for (int ni = 0; ni < 4; ni++) {
            int r0 = bm + wrow + mi * 16 + g;
            int c  = bn + wcol + ni * 8 + 2 * t;
            *reinterpret_cast<float2*>(&out[(size_t)r0 * CC + c]) =
                make_float2(acc[mi][ni][0], acc[mi][ni][1]);
            *reinterpret_cast<float2*>(&out[(size_t)(r0 + 8) * CC + c]) =
                make_float2(acc[mi][ni][2], acc[mi][ni][3]);
        }
}

// ---------------- gate GEMM (K=2C) + fused surprise epilogue -> upd ----------------
__global__ void __launch_bounds__(256) gemm_gate(const float* __restrict__ bg)
{
    extern __shared__ char smem_g[];
    const unsigned sbase = smem_u32(smem_g);
    const int tid = threadIdx.x, warp = tid >> 5, lane = tid & 31;
    const int wrow = (warp >> 2) * 64, wcol = (warp & 3) * 32;
    const int bm = blockIdx.y * 128, bn = blockIdx.x * 128;

    float acc[4][4][4];
#pragma unroll
    for (int i = 0; i < 4; i++)
#pragma unroll
        for (int j = 0; j < 4; j++)
#pragma unroll
            for (int k = 0; k < 4; k++) acc[i][j][k] = 0.f;

    gemm_mainloop(g_retrb, g_pb, g_Wgb, 2 * CC, bm, bn, sbase, tid, wrow, wcol, lane, acc);

    const int g = lane >> 2, t = lane & 3;
#pragma unroll
    for (int mi = 0; mi < 4; mi++)
#pragma unroll
        for (int ni = 0; ni < 4; ni++) {
            int cl = wcol + ni * 8 + 2 * t;
            int gc = bn + cl;
            float e0 = g_etas[gc], e1 = g_etas[gc + 1];
            float b0 = bg[gc],     b1 = bg[gc + 1];
#pragma unroll
            for (int hh = 0; hh < 2; hh++) {
                int r = bm + wrow + mi * 16 + g + hh * 8;
                size_t gi = (size_t)r * CC + gc;
                float2 wv2 = *reinterpret_cast<const float2*>(&g_WV[gi]);
                __nv_bfloat162 rb2 = *reinterpret_cast<const __nv_bfloat162*>(&g_retrb[gi]);
                float2 rt2 = __bfloat1622float2(rb2);
                float s0 = 1.f / (1.f + __expf(-(acc[mi][ni][hh*2+0] + b0)));
                float s1 = 1.f / (1.f + __expf(-(acc[mi][ni][hh*2+1] + b1)));
                *reinterpret_cast<float2*>(&g_upd[gi]) =
                    make_float2(e0 * s0 * (wv2.x - rt2.x), e1 * s1 * (wv2.y - rt2.y));
            }
        }
}

// ---------------- M update: M_new = M + ww_m * upd_c (one CTA per batch row) ----------------
__global__ void __launch_bounds__(256) mupd_kernel(
    const float* __restrict__ Mm, float* __restrict__ mnew)
{
    const int b = blockIdx.x;
    __shared__ float us[CC];
    __shared__ float wws[NSLOT];
    const int tid = threadIdx.x;
    ((float2*)us)[tid] = ((const float2*)(g_upd + (size_t)b * CC))[tid];
    if (tid < NSLOT) wws[tid] = g_ww[(size_t)b * NSLOT + tid];
    __syncthreads();

    const float4* M4 = (const float4*)(Mm + (size_t)b * NSLOT * CC);
    float4* O4 = (float4*)(mnew + (size_t)b * NSLOT * CC);
#pragma unroll 4
    for (int idx = tid; idx < NSLOT * CC / 4; idx += 256) {
        const int m = idx >> 7, c4 = idx & 127;
        const float w = wws[m];
        float4 mv = __ldcs(M4 + idx);
        float4 u = ((const float4*)us)[c4];
        float4 o;
        o.x = mv.x + w * u.x;
        o.y = mv.y + w * u.y;
        o.z = mv.z + w * u.z;
        o.w = mv.w + w * u.w;
        __stcs(O4 + idx, o);
    }
}

// ---------------- fused attention / retrieval / Mk_new ----------------
__global__ void __launch_bounds__(256) attn_kernel(
    const float* __restrict__ h, const float* __restrict__ Mk,
    const float* __restrict__ Mm, float* __restrict__ out)
{
    const int b = blockIdx.x;
    __shared__ float qs[CC], wks[CC];
    __shared__ float sm[NSLOT], tm[NSLOT], attnv[NSLOT], wws[NSLOT];

    const int tid = threadIdx.x;
    const int warp = tid >> 5, lane = tid & 31;
    const float* Mkb = Mk + (size_t)b * NSLOT * CC;
    const float* Mb  = Mm + (size_t)b * NSLOT * CC;

#pragma unroll
    for (int i = 0; i < 2; i++) {
        qs [tid + i * 256] = g_Q [(size_t)b * CC + tid + i * 256];
        wks[tid + i * 256] = g_WK[(size_t)b * CC + tid + i * 256];
    }
    __syncthreads();

    // dual dot products vs M_keys rows (warp -> 4 slots)
#pragma unroll
    for (int mm = 0; mm < 4; mm++) {
        const int m = warp * 4 + mm;
        const float4* row4 = (const float4*)(Mkb + (size_t)m * CC);
        float s = 0.f, tt = 0.f;
#pragma unroll
        for (int it = 0; it < 4; it++) {
            float4 v = row4[lane + it * 32];
            float4 q = ((const float4*)qs)[lane + it * 32];
            float4 w = ((const float4*)wks)[lane + it * 32];
            s  += v.x*q.x + v.y*q.y + v.z*q.z + v.w*q.w;
            tt += v.x*w.x + v.y*w.y + v.z*w.z + v.w*w.w;
        }
#pragma unroll
        for (int o = 16; o > 0; o >>= 1) {
            s  += __shfl_xor_sync(0xffffffffu, s,  o);
            tt += __shfl_xor_sync(0xffffffffu, tt, o);
        }
        if (lane == 0) { sm[m] = s; tm[m] = tt; }
    }
    __syncthreads();

    if (tid < 32) {
        const float isq = 1.0f / sqrtf((float)CC);
        float s = sm[tid] * isq;
        float w = tm[tid] * isq;
        float mx = s;
#pragma unroll
        for (int o = 16; o > 0; o >>= 1) mx = fmaxf(mx, __shfl_xor_sync(0xffffffffu, mx, o));
        float e = expf(s - mx), sum = e;
#pragma unroll
        for (int o = 16; o > 0; o >>= 1) sum += __shfl_xor_sync(0xffffffffu, sum, o);
        attnv[tid] = e / sum;

        float mx2 = w;
#pragma unroll
        for (int o = 16; o > 0; o >>= 1) mx2 = fmaxf(mx2, __shfl_xor_sync(0xffffffffu, mx2, o));
        float e2 = expf(w - mx2), sum2 = e2;
#pragma unroll
        for (int o = 16; o > 0; o >>= 1) sum2 += __shfl_xor_sync(0xffffffffu, sum2, o);
        const float wv = e2 / sum2;
        wws[tid] = wv;
        g_ww[(size_t)b * NSLOT + tid] = wv;
    }
    __syncthreads();

    // Mk_new FIRST (Mk hot in L2 from the dot-product phase)
    {
        float* mkout = out + (size_t)BB * CC + (size_t)BB * NSLOT * CC + (size_t)b * NSLOT * CC;
        const float4* Mk4 = (const float4*)Mkb;
        float4* mo4 = (float4*)mkout;
        for (int idx = tid; idx < NSLOT * CC / 4; idx += 256) {
            const int m = idx >> 7;
            const int c4 = idx & 127;
            float4 mk = Mk4[idx];
            float4 wk = ((const float4*)wks)[c4];
            float w = wws[m] * 0.01f;
            float4 o;
            o.x = mk.x + w * (wk.x - mk.x);
            o.y = mk.y + w * (wk.y - mk.y);
            o.z = mk.z + w * (wk.z - mk.z);
            o.w = mk.w + w * (wk.w - mk.w);
            __stcs(mo4 + idx, o);
        }
    }

    // retrieval (streams M, evict-first) + out + bf16 retr for gate GEMM
    {
        const float2* M2 = (const float2*)Mb;
        float2 r = make_float2(0.f, 0.f);
#pragma unroll
        for (int m = 0; m < NSLOT; m++) {
            float2 v = __ldcs(M2 + m * (CC / 2) + tid);
            r.x += attnv[m] * v.x;
            r.y += attnv[m] * v.y;
        }
        const float2* h2 = (const float2*)(h + (size_t)b * CC);
        float2 hv = h2[tid];
        __stcs((float2*)(out + (size_t)b * CC) + tid, make_float2(hv.x + r.x, hv.y + r.y));
        __nv_bfloat162 rb = __floats2bfloat162_rn(r.x, r.y);
        ((__nv_bfloat162*)(g_retrb + (size_t)b * CC))[tid] = rb;
    }
}

// ---------------- launch ----------------
extern "C" void kernel_launch(void* const* d_in, const int* in_sizes, int n_in,
                              void* d_out, int out_size)
{
    const float* h   = (const float*)d_in[0];
    const float* p   = (const float*)d_in[1];
    const float* M   = (const float*)d_in[2];
    const float* Mk  = (const float*)d_in[3];
    const float* Wq  = (const float*)d_in[4];
    const float* Wk  = (const float*)d_in[5];
    const float* Wv  = (const float*)d_in[6];
    const float* Wg  = (const float*)d_in[7];
    const float* bg  = (const float*)d_in[8];
    const float* eta = (const float*)d_in[9];
    float* out = (float*)d_out;

    static int configured = 0;
    if (!configured) {
        cudaFuncSetAttribute(gemm_proj, cudaFuncAttributeMaxDynamicSharedMemorySize, 61440);
        cudaFuncSetAttribute(gemm_gate, cudaFuncAttributeMaxDynamicSharedMemorySize, 61440);
        configured = 1;
    }

    // 1. bf16 conversion (+ eta sigmoid)
    convert_kernel<<<9472, 256>>>(h, p, Wq, Wk, Wv, Wg, eta);

    // 2. Q / write_k / write_v projections (batched over z)
    gemm_proj<<<dim3(4, 64, 3), 256, 61440>>>();

    // 3. fused attention / retrieval / out / Mk_new
    attn_kernel<<<BB, 256>>>(h, Mk, M, out);

    // 4. gate GEMM with fused surprise epilogue -> upd
    gemm_gate<<<dim3(4, 64, 1), 256, 61440>>>(bg);

    // 5. balanced M_new streaming (one CTA per batch row)
    mupd_kernel<<<BB, 256>>>(M, out + (size_t)BB * CC);
}